// round 5
// baseline (speedup 1.0000x reference)
#include <cuda_runtime.h>
#include <cstdint>

#define HEADS 6
#define HD 32
#define CDIM 192
#define NQ 576
#define DISP 4
#define IMG 256
#define BATCH 4
#define TOK 64
#define NWIN 1024
#define MTOT (BATCH * IMG * IMG)
#define ATT_SCALE 0.17677669529663687f

// scratch (allocation-free rule: __device__ globals)
__device__ float g_qkv[(size_t)MTOT * NQ];     // ROLLED coords, [m, 576]
__device__ float g_attn[(size_t)MTOT * CDIM];  // ROLLED coords, [m, 192]
__device__ float g_bias[TOK * TOK];

// ---------------------------------------------------------------------------
// mma.sync helpers (HMMA path — compiles for compute_103)
// ---------------------------------------------------------------------------
__device__ __forceinline__ uint32_t f2tf32(float f) {
    uint32_t r;
    asm("cvt.rna.tf32.f32 %0, %1;" : "=r"(r) : "f"(f));
    return r;
}
__device__ __forceinline__ void mma_tf32(float* c, const uint32_t* a, const uint32_t* b) {
    asm volatile(
        "mma.sync.aligned.m16n8k8.row.col.f32.tf32.tf32.f32 "
        "{%0,%1,%2,%3}, {%4,%5,%6,%7}, {%8,%9}, {%0,%1,%2,%3};"
        : "+f"(c[0]), "+f"(c[1]), "+f"(c[2]), "+f"(c[3])
        : "r"(a[0]), "r"(a[1]), "r"(a[2]), "r"(a[3]), "r"(b[0]), "r"(b[1]));
}

#define AST 196                       // smem row stride (words): bank = 4*lr+lc, conflict-free
#define A_WORDS (128 * AST)
#define B_WORDS (64 * AST)
#define SMEM_BYTES ((A_WORDS + 2 * B_WORDS) * 4)   // 200704 B: A + double-buffered B

// ---------------------------------------------------------------------------
// Kernel 0: gather rel-pos bias table
// ---------------------------------------------------------------------------
__global__ void bias_kernel(const float* __restrict__ pos) {
    int idx = blockIdx.x * blockDim.x + threadIdx.x;
    if (idx < TOK * TOK) {
        int i = idx >> 6, j = idx & 63;
        g_bias[idx] = pos[((i >> 3) - (j >> 3) + 7) * 15 + ((i & 7) - (j & 7) + 7)];
    }
}

// ---------------------------------------------------------------------------
// Shared GEMM body pieces (qkv / out differ only in A source, tile count,
// and epilogue) — kept as two kernels for clarity.
// 512 threads, 16 warps, warp grid 4x4, warp tile 32x16 on BM=128 x BN=64.
// ---------------------------------------------------------------------------

// ---------------------------------------------------------------------------
// Kernel 1: QKV GEMM (mma.sync tf32). Roll folded into A-load; g_qkv rolled.
// ---------------------------------------------------------------------------
__global__ __launch_bounds__(512) void qkv_tc(const float* __restrict__ x,
                                              const float* __restrict__ wqkv) {
    extern __shared__ uint32_t sm[];
    uint32_t* As = sm;                       // [128][196]
    uint32_t* Bbuf[2] = { sm + A_WORDS, sm + A_WORDS + B_WORDS };

    int tid = threadIdx.x;
    int wid = tid >> 5, lane = tid & 31;
    int warp_m = (wid >> 2) * 32;
    int warp_n = (wid & 3) * 16;
    int lr = lane >> 2, lc = lane & 3;
    int m0 = blockIdx.x * 128;

    // A tile: 128x192, roll folded in, cvt to tf32. 6144 float4 / 512 thr.
    #pragma unroll
    for (int j = 0; j < 12; j++) {
        int i = tid + j * 512;
        int r = i / 48, c4 = i % 48;
        int m = m0 + r;
        int bb = m >> 16, y = (m >> 8) & 255, xx = m & 255;
        int ys = (y + DISP) & 255, xs = (xx + DISP) & 255;
        float4 v = *(const float4*)(x + ((size_t)((bb * IMG + ys) * IMG + xs)) * CDIM + c4 * 4);
        *(uint4*)&As[r * AST + c4 * 4] =
            make_uint4(f2tf32(v.x), f2tf32(v.y), f2tf32(v.z), f2tf32(v.w));
    }
    // B tile 0: 3072 float4 / 512 thr.
    #pragma unroll
    for (int j = 0; j < 6; j++) {
        int i = tid + j * 512;
        int r = i / 48, c4 = i % 48;
        float4 v = *(const float4*)(wqkv + (size_t)r * CDIM + c4 * 4);
        *(uint4*)&Bbuf[0][r * AST + c4 * 4] =
            make_uint4(f2tf32(v.x), f2tf32(v.y), f2tf32(v.z), f2tf32(v.w));
    }
    __syncthreads();

    for (int t = 0; t < 9; t++) {
        int n0 = t * 64;
        // Prefetch next B tile into registers (overlaps with compute).
        float4 pf[6];
        if (t < 8) {
            int n1 = n0 + 64;
            #pragma unroll
            for (int j = 0; j < 6; j++) {
                int i = tid + j * 512;
                int r = i / 48, c4 = i % 48;
                pf[j] = *(const float4*)(wqkv + (size_t)(n1 + r) * CDIM + c4 * 4);
            }
        }

        const uint32_t* Bc = Bbuf[t & 1];
        float acc[2][2][4] = {};
        #pragma unroll
        for (int k0 = 0; k0 < CDIM; k0 += 8) {
            uint32_t a[2][4], b[2][2];
            #pragma unroll
            for (int mt = 0; mt < 2; mt++) {
                int row = warp_m + mt * 16 + lr;
                a[mt][0] = As[row * AST + k0 + lc];
                a[mt][1] = As[(row + 8) * AST + k0 + lc];
                a[mt][2] = As[row * AST + k0 + lc + 4];
                a[mt][3] = As[(row + 8) * AST + k0 + lc + 4];
            }
            #pragma unroll
            for (int nt = 0; nt < 2; nt++) {
                int col = warp_n + nt * 8 + lr;
                b[nt][0] = Bc[col * AST + k0 + lc];
                b[nt][1] = Bc[col * AST + k0 + lc + 4];
            }
            #pragma unroll
            for (int mt = 0; mt < 2; mt++)
                #pragma unroll
                for (int nt = 0; nt < 2; nt++)
                    mma_tf32(acc[mt][nt], a[mt], b[nt]);
        }

        // Store prefetched B into the other buffer.
        if (t < 8) {
            uint32_t* Bn = Bbuf[(t + 1) & 1];
            #pragma unroll
            for (int j = 0; j < 6; j++) {
                int i = tid + j * 512;
                int r = i / 48, c4 = i % 48;
                *(uint4*)&Bn[r * AST + c4 * 4] =
                    make_uint4(f2tf32(pf[j].x), f2tf32(pf[j].y), f2tf32(pf[j].z), f2tf32(pf[j].w));
            }
        }

        // Epilogue: natural [m][576] layout.
        #pragma unroll
        for (int mt = 0; mt < 2; mt++) {
            size_t r0 = (size_t)(m0 + warp_m + mt * 16 + lr) * NQ + n0 + warp_n;
            size_t r1 = r0 + 8 * NQ;
            #pragma unroll
            for (int nt = 0; nt < 2; nt++) {
                int col = nt * 8 + lc * 2;
                *(float2*)(g_qkv + r0 + col) = make_float2(acc[mt][nt][0], acc[mt][nt][1]);
                *(float2*)(g_qkv + r1 + col) = make_float2(acc[mt][nt][2], acc[mt][nt][3]);
            }
        }
        __syncthreads();
    }
}

// ---------------------------------------------------------------------------
// Kernel 2: windowed attention (g_qkv already rolled — direct window coords).
// ---------------------------------------------------------------------------
__global__ __launch_bounds__(64) void attn_kernel() {
    __shared__ float ks[TOK * HD];
    __shared__ float vs[TOK * HD];
    __shared__ float bs[TOK * 65];

    int bid = blockIdx.x;
    int win = bid & (NWIN - 1);
    int hb = bid >> 10;
    int head = hb % HEADS;
    int bb = hb / HEADS;
    int tid = threadIdx.x;
    int wy = win >> 5, wx = win & 31;

    #pragma unroll
    for (int it = 0; it < 8; it++) {
        int j = it * 8 + (tid >> 3);
        int ys = wy * 8 + (j >> 3);
        int xs = wx * 8 + (j & 7);
        size_t src = ((size_t)((bb * IMG + ys) * IMG + xs)) * NQ + head * HD + (tid & 7) * 4;
        *(float4*)(ks + j * HD + (tid & 7) * 4) = *(const float4*)(g_qkv + CDIM + src);
        *(float4*)(vs + j * HD + (tid & 7) * 4) = *(const float4*)(g_qkv + 2 * CDIM + src);
    }
    for (int idx = tid; idx < TOK * TOK / 4; idx += 64) {
        float4 v = *(const float4*)(g_bias + idx * 4);
        int i = (idx * 4) >> 6, j = (idx * 4) & 63;
        float* dst = bs + i * 65 + j;
        dst[0] = v.x; dst[1] = v.y; dst[2] = v.z; dst[3] = v.w;
    }

    float qv[HD];
    {
        int ys = wy * 8 + (tid >> 3);
        int xs = wx * 8 + (tid & 7);
        const float* qp = g_qkv + ((size_t)((bb * IMG + ys) * IMG + xs)) * NQ + head * HD;
        #pragma unroll
        for (int d4 = 0; d4 < 8; d4++) {
            float4 v = *(const float4*)(qp + d4 * 4);
            qv[d4 * 4] = v.x; qv[d4 * 4 + 1] = v.y; qv[d4 * 4 + 2] = v.z; qv[d4 * 4 + 3] = v.w;
        }
    }
    __syncthreads();

    float sc[TOK];
    float mx = -1e30f;
    #pragma unroll
    for (int j = 0; j < TOK; j++) {
        float a = 0.f;
        #pragma unroll
        for (int d4 = 0; d4 < 8; d4++) {
            float4 kv = *(const float4*)(ks + j * HD + d4 * 4);
            a += qv[d4 * 4] * kv.x + qv[d4 * 4 + 1] * kv.y
               + qv[d4 * 4 + 2] * kv.z + qv[d4 * 4 + 3] * kv.w;
        }
        a = a * ATT_SCALE + bs[tid * 65 + j];
        sc[j] = a;
        mx = fmaxf(mx, a);
    }
    float sum = 0.f;
    #pragma unroll
    for (int j = 0; j < TOK; j++) { float e = __expf(sc[j] - mx); sc[j] = e; sum += e; }
    float inv = 1.f / sum;

    float ov[HD];
    #pragma unroll
    for (int d = 0; d < HD; d++) ov[d] = 0.f;
    #pragma unroll
    for (int j = 0; j < TOK; j++) {
        float p = sc[j] * inv;
        #pragma unroll
        for (int d4 = 0; d4 < 8; d4++) {
            float4 vv = *(const float4*)(vs + j * HD + d4 * 4);
            ov[d4 * 4] += p * vv.x; ov[d4 * 4 + 1] += p * vv.y;
            ov[d4 * 4 + 2] += p * vv.z; ov[d4 * 4 + 3] += p * vv.w;
        }
    }

    int y = wy * 8 + (tid >> 3);
    int xx = wx * 8 + (tid & 7);
    float* op = g_attn + ((size_t)(bb * IMG + y) * IMG + xx) * CDIM + head * HD;
    #pragma unroll
    for (int d4 = 0; d4 < 8; d4++)
        *(float4*)(op + d4 * 4) =
            make_float4(ov[d4 * 4], ov[d4 * 4 + 1], ov[d4 * 4 + 2], ov[d4 * 4 + 3]);
}

// ---------------------------------------------------------------------------
// Kernel 3: output projection (mma.sync tf32) + bias; roll-back on store.
// ---------------------------------------------------------------------------
__global__ __launch_bounds__(512) void out_tc(const float* __restrict__ wout,
                                              const float* __restrict__ bout,
                                              float* __restrict__ out) {
    extern __shared__ uint32_t sm[];
    uint32_t* As = sm;
    uint32_t* Bbuf[2] = { sm + A_WORDS, sm + A_WORDS + B_WORDS };

    int tid = threadIdx.x;
    int wid = tid >> 5, lane = tid & 31;
    int warp_m = (wid >> 2) * 32;
    int warp_n = (wid & 3) * 16;
    int lr = lane >> 2, lc = lane & 3;
    int m0 = blockIdx.x * 128;

    #pragma unroll
    for (int j = 0; j < 12; j++) {
        int i = tid + j * 512;
        int r = i / 48, c4 = i % 48;
        float4 v = *(const float4*)(g_attn + (size_t)(m0 + r) * CDIM + c4 * 4);
        *(uint4*)&As[r * AST + c4 * 4] =
            make_uint4(f2tf32(v.x), f2tf32(v.y), f2tf32(v.z), f2tf32(v.w));
    }
    #pragma unroll
    for (int j = 0; j < 6; j++) {
        int i = tid + j * 512;
        int r = i / 48, c4 = i % 48;
        float4 v = *(const float4*)(wout + (size_t)r * CDIM + c4 * 4);
        *(uint4*)&Bbuf[0][r * AST + c4 * 4] =
            make_uint4(f2tf32(v.x), f2tf32(v.y), f2tf32(v.z), f2tf32(v.w));
    }
    __syncthreads();

    for (int t = 0; t < 3; t++) {
        int n0 = t * 64;
        float4 pf[6];
        if (t < 2) {
            int n1 = n0 + 64;
            #pragma unroll
            for (int j = 0; j < 6; j++) {
                int i = tid + j * 512;
                int r = i / 48, c4 = i % 48;
                pf[j] = *(const float4*)(wout + (size_t)(n1 + r) * CDIM + c4 * 4);
            }
        }

        const uint32_t* Bc = Bbuf[t & 1];
        float acc[2][2][4] = {};
        #pragma unroll
        for (int k0 = 0; k0 < CDIM; k0 += 8) {
            uint32_t a[2][4], b[2][2];
            #pragma unroll
            for (int mt = 0; mt < 2; mt++) {
                int row = warp_m + mt * 16 + lr;
                a[mt][0] = As[row * AST + k0 + lc];
                a[mt][1] = As[(row + 8) * AST + k0 + lc];
                a[mt][2] = As[row * AST + k0 + lc + 4];
                a[mt][3] = As[(row + 8) * AST + k0 + lc + 4];
            }
            #pragma unroll
            for (int nt = 0; nt < 2; nt++) {
                int col = warp_n + nt * 8 + lr;
                b[nt][0] = Bc[col * AST + k0 + lc];
                b[nt][1] = Bc[col * AST + k0 + lc + 4];
            }
            #pragma unroll
            for (int mt = 0; mt < 2; mt++)
                #pragma unroll
                for (int nt = 0; nt < 2; nt++)
                    mma_tf32(acc[mt][nt], a[mt], b[nt]);
        }

        if (t < 2) {
            uint32_t* Bn = Bbuf[(t + 1) & 1];
            #pragma unroll
            for (int j = 0; j < 6; j++) {
                int i = tid + j * 512;
                int r = i / 48, c4 = i % 48;
                *(uint4*)&Bn[r * AST + c4 * 4] =
                    make_uint4(f2tf32(pf[j].x), f2tf32(pf[j].y), f2tf32(pf[j].z), f2tf32(pf[j].w));
            }
        }

        // Epilogue: bias + roll-back scatter.
        #pragma unroll
        for (int mt = 0; mt < 2; mt++) {
            #pragma unroll
            for (int half = 0; half < 2; half++) {
                int m = m0 + warp_m + mt * 16 + lr + half * 8;
                int bb = m >> 16, y = (m >> 8) & 255, xx = m & 255;
                int yf = (y + DISP) & 255, xf = (xx + DISP) & 255;
                float* op = out + ((size_t)(bb * IMG + yf) * IMG + xf) * CDIM + n0 + warp_n;
                #pragma unroll
                for (int nt = 0; nt < 2; nt++) {
                    int col = nt * 8 + lc * 2;
                    float b0 = bout[n0 + warp_n + col];
                    float b1 = bout[n0 + warp_n + col + 1];
                    *(float2*)(op + col) = make_float2(acc[mt][nt][half * 2] + b0,
                                                       acc[mt][nt][half * 2 + 1] + b1);
                }
            }
        }
        __syncthreads();
    }
}

// ---------------------------------------------------------------------------
extern "C" void kernel_launch(void* const* d_in, const int* in_sizes, int n_in,
                              void* d_out, int out_size) {
    const float* x    = (const float*)d_in[0];
    const float* wqkv = (const float*)d_in[1];
    const float* pos  = (const float*)d_in[2];
    const float* wout = (const float*)d_in[3];
    const float* bout = (const float*)d_in[4];
    float* out = (float*)d_out;

    cudaFuncSetAttribute(qkv_tc, cudaFuncAttributeMaxDynamicSharedMemorySize, SMEM_BYTES);
    cudaFuncSetAttribute(out_tc, cudaFuncAttributeMaxDynamicSharedMemorySize, SMEM_BYTES);

    bias_kernel<<<16, 256>>>(pos);
    qkv_tc<<<MTOT / 128, 512, SMEM_BYTES>>>(x, wqkv);
    attn_kernel<<<BATCH * HEADS * NWIN, 64>>>();
    out_tc<<<MTOT / 128, 512, SMEM_BYTES>>>(wout, bout, out);
}

// round 7
// speedup vs baseline: 1.6357x; 1.6357x over previous
#include <cuda_runtime.h>
#include <cstdint>

#define HEADS 6
#define HD 32
#define CDIM 192
#define NQ 576
#define DISP 4
#define IMG 256
#define BATCH 4
#define TOK 64
#define NWIN 1024
#define MTOT (BATCH * IMG * IMG)
#define ATT_SCALE 0.17677669529663687f

// scratch (allocation-free rule: __device__ globals)
__device__ float g_qkv[(size_t)MTOT * NQ];     // ROLLED coords, [m, 576]
__device__ float g_attn[(size_t)MTOT * CDIM];  // ROLLED coords, [m, 192]
__device__ float g_bias[TOK * TOK];

// ---------------------------------------------------------------------------
// mma.sync helpers
// ---------------------------------------------------------------------------
__device__ __forceinline__ uint32_t f2tf32(float f) {
    uint32_t r;
    asm("cvt.rna.tf32.f32 %0, %1;" : "=r"(r) : "f"(f));
    return r;
}
__device__ __forceinline__ void mma_tf32(float* c, const uint32_t* a, const uint32_t* b) {
    asm volatile(
        "mma.sync.aligned.m16n8k8.row.col.f32.tf32.tf32.f32 "
        "{%0,%1,%2,%3}, {%4,%5,%6,%7}, {%8,%9}, {%0,%1,%2,%3};"
        : "+f"(c[0]), "+f"(c[1]), "+f"(c[2]), "+f"(c[3])
        : "r"(a[0]), "r"(a[1]), "r"(a[2]), "r"(a[3]), "r"(b[0]), "r"(b[1]));
}

// GEMM smem: BM=64 rows A + 64 rows B, stride 196 words (4*row+lc banking).
#define AST 196
#define A_WORDS (64 * AST)
#define SMEM_BYTES (2 * A_WORDS * 4)   // 100352 B -> 2 CTAs/SM

// ---------------------------------------------------------------------------
// Kernel 0: gather rel-pos bias table
// ---------------------------------------------------------------------------
__global__ void bias_kernel(const float* __restrict__ pos) {
    int idx = blockIdx.x * blockDim.x + threadIdx.x;
    if (idx < TOK * TOK) {
        int i = idx >> 6, j = idx & 63;
        g_bias[idx] = pos[((i >> 3) - (j >> 3) + 7) * 15 + ((i & 7) - (j & 7) + 7)];
    }
}

// ---------------------------------------------------------------------------
// Kernel 1: QKV GEMM. BM=64, 128 thr, 4 warps (2m x 2n), warp tile 32x32.
// Roll folded into A-load; g_qkv in ROLLED coords.
// ---------------------------------------------------------------------------
__global__ __launch_bounds__(128) void qkv_tc(const float* __restrict__ x,
                                              const float* __restrict__ wqkv) {
    extern __shared__ uint32_t sm[];
    uint32_t* As = sm;
    uint32_t* Bs = sm + A_WORDS;

    int tid = threadIdx.x;
    int wid = tid >> 5, lane = tid & 31;
    int warp_m = (wid >> 1) * 32;
    int warp_n = (wid & 1) * 32;
    int lr = lane >> 2, lc = lane & 3;
    int m0 = blockIdx.x * 64;

    // A tile 64x192, roll folded in. 3072 float4 / 128 thr = 24 each.
    #pragma unroll
    for (int j = 0; j < 24; j++) {
        int i = tid + j * 128;
        int r = i / 48, c4 = i % 48;
        int m = m0 + r;
        int bb = m >> 16, y = (m >> 8) & 255, xx = m & 255;
        int ys = (y + DISP) & 255, xs = (xx + DISP) & 255;
        float4 v = *(const float4*)(x + ((size_t)((bb * IMG + ys) * IMG + xs)) * CDIM + c4 * 4);
        *(uint4*)&As[r * AST + c4 * 4] =
            make_uint4(f2tf32(v.x), f2tf32(v.y), f2tf32(v.z), f2tf32(v.w));
    }

    for (int t = 0; t < 9; t++) {
        int n0 = t * 64;
        __syncthreads();   // prev-tile readers done (covers A-load on t=0 too)
        #pragma unroll
        for (int j = 0; j < 24; j++) {
            int i = tid + j * 128;
            int r = i / 48, c4 = i % 48;
            float4 v = *(const float4*)(wqkv + (size_t)(n0 + r) * CDIM + c4 * 4);
            *(uint4*)&Bs[r * AST + c4 * 4] =
                make_uint4(f2tf32(v.x), f2tf32(v.y), f2tf32(v.z), f2tf32(v.w));
        }
        __syncthreads();

        float acc[2][4][4] = {};
        #pragma unroll
        for (int k0 = 0; k0 < CDIM; k0 += 8) {
            uint32_t a[2][4], b[4][2];
            #pragma unroll
            for (int mt = 0; mt < 2; mt++) {
                int row = warp_m + mt * 16 + lr;
                a[mt][0] = As[row * AST + k0 + lc];
                a[mt][1] = As[(row + 8) * AST + k0 + lc];
                a[mt][2] = As[row * AST + k0 + lc + 4];
                a[mt][3] = As[(row + 8) * AST + k0 + lc + 4];
            }
            #pragma unroll
            for (int nt = 0; nt < 4; nt++) {
                int col = warp_n + nt * 8 + lr;
                b[nt][0] = Bs[col * AST + k0 + lc];
                b[nt][1] = Bs[col * AST + k0 + lc + 4];
            }
            #pragma unroll
            for (int mt = 0; mt < 2; mt++)
                #pragma unroll
                for (int nt = 0; nt < 4; nt++)
                    mma_tf32(acc[mt][nt], a[mt], b[nt]);
        }

        #pragma unroll
        for (int mt = 0; mt < 2; mt++) {
            size_t r0 = (size_t)(m0 + warp_m + mt * 16 + lr) * NQ + n0 + warp_n;
            size_t r1 = r0 + 8 * NQ;
            #pragma unroll
            for (int nt = 0; nt < 4; nt++) {
                int col = nt * 8 + lc * 2;
                *(float2*)(g_qkv + r0 + col) = make_float2(acc[mt][nt][0], acc[mt][nt][1]);
                *(float2*)(g_qkv + r1 + col) = make_float2(acc[mt][nt][2], acc[mt][nt][3]);
            }
        }
    }
}

// ---------------------------------------------------------------------------
// Kernel 2: windowed attention via HMMA. Block = (b, win, head), 128 thr,
// 4 warps x 16 q-rows. S = Q K^T (m16n8k8 tf32), quad-shuffle softmax,
// P routed through smem (overlaying Q/K), then P x V with V^T in smem.
// ---------------------------------------------------------------------------
#define QST 36                 // Q/K smem row stride (words): 4*lr+lc banking
#define PST 68                 // P / V^T row stride
#define BST 68                 // bias row stride (mult. of 4 -> float4-aligned; 68%32=4 -> conflict-free)

__global__ __launch_bounds__(128) void attn_mma() {
    __shared__ float pool[64 * QST * 2];   // Q[64][36] + K[64][36]; overlaid by P[64][68]
    __shared__ float vt[32 * PST];         // V^T [32][68]
    __shared__ float bsm[64 * BST];        // bias [64][68]

    uint32_t* Qs = (uint32_t*)pool;
    uint32_t* Ks = (uint32_t*)pool + 64 * QST;
    uint32_t* Ps = (uint32_t*)pool;        // overlay (after __syncthreads)
    uint32_t* VT = (uint32_t*)vt;

    int bid = blockIdx.x;
    int head = bid % HEADS;
    int t2 = bid / HEADS;
    int win = t2 & (NWIN - 1);
    int bb = t2 >> 10;
    int wy = win >> 5, wx = win & 31;

    int tid = threadIdx.x;
    int wid = tid >> 5, lane = tid & 31;
    int lr = lane >> 2, lc = lane & 3;
    int r_base = wid * 16;                 // warp's q-row block

    // ---- load Q, K (tf32), V transposed (tf32), bias (fp32) ----
    #pragma unroll
    for (int l = 0; l < 4; l++) {
        int idx = tid + l * 128;           // 0..511
        int j = idx >> 3, d4 = idx & 7;    // token, float4-chunk of d
        int y = wy * 8 + (j >> 3), xx = wx * 8 + (j & 7);
        size_t base = ((size_t)((bb * IMG + y) * IMG + xx)) * NQ + head * HD + d4 * 4;
        float4 q = *(const float4*)(g_qkv + base);
        float4 k = *(const float4*)(g_qkv + base + CDIM);
        float4 v = *(const float4*)(g_qkv + base + 2 * CDIM);
        Qs[j * QST + d4 * 4 + 0] = f2tf32(q.x); Qs[j * QST + d4 * 4 + 1] = f2tf32(q.y);
        Qs[j * QST + d4 * 4 + 2] = f2tf32(q.z); Qs[j * QST + d4 * 4 + 3] = f2tf32(q.w);
        Ks[j * QST + d4 * 4 + 0] = f2tf32(k.x); Ks[j * QST + d4 * 4 + 1] = f2tf32(k.y);
        Ks[j * QST + d4 * 4 + 2] = f2tf32(k.z); Ks[j * QST + d4 * 4 + 3] = f2tf32(k.w);
        VT[(d4 * 4 + 0) * PST + j] = f2tf32(v.x);
        VT[(d4 * 4 + 1) * PST + j] = f2tf32(v.y);
        VT[(d4 * 4 + 2) * PST + j] = f2tf32(v.z);
        VT[(d4 * 4 + 3) * PST + j] = f2tf32(v.w);
    }
    #pragma unroll
    for (int l = 0; l < 8; l++) {
        int w0 = (tid + l * 128) * 4;      // word index in 64x64
        int row = w0 >> 6, col = w0 & 63;
        float4 v = *(const float4*)(g_bias + w0);
        *(float4*)(bsm + row * BST + col) = v;
    }
    __syncthreads();

    // ---- S = Q K^T * scale + bias ----
    uint32_t a[4][4];                      // A-frags for all 4 k-steps (hoisted)
    #pragma unroll
    for (int kk = 0; kk < 4; kk++) {
        int k0 = kk * 8;
        a[kk][0] = Qs[(r_base + lr) * QST + k0 + lc];
        a[kk][1] = Qs[(r_base + 8 + lr) * QST + k0 + lc];
        a[kk][2] = Qs[(r_base + lr) * QST + k0 + lc + 4];
        a[kk][3] = Qs[(r_base + 8 + lr) * QST + k0 + lc + 4];
    }
    float s[8][4] = {};
    #pragma unroll
    for (int nt = 0; nt < 8; nt++) {
        #pragma unroll
        for (int kk = 0; kk < 4; kk++) {
            int k0 = kk * 8;
            uint32_t b[2];
            b[0] = Ks[(nt * 8 + lr) * QST + k0 + lc];
            b[1] = Ks[(nt * 8 + lr) * QST + k0 + lc + 4];
            mma_tf32(s[nt], a[kk], b);
        }
    }
    // scale + bias
    int row0 = r_base + lr, row1 = r_base + lr + 8;
    #pragma unroll
    for (int nt = 0; nt < 8; nt++) {
        int col = nt * 8 + lc * 2;
        float2 b0 = *(const float2*)(bsm + row0 * BST + col);
        float2 b1 = *(const float2*)(bsm + row1 * BST + col);
        s[nt][0] = s[nt][0] * ATT_SCALE + b0.x;
        s[nt][1] = s[nt][1] * ATT_SCALE + b0.y;
        s[nt][2] = s[nt][2] * ATT_SCALE + b1.x;
        s[nt][3] = s[nt][3] * ATT_SCALE + b1.y;
    }

    // ---- softmax (rows row0, row1; quad = lanes sharing lr) ----
    float mx0 = -1e30f, mx1 = -1e30f;
    #pragma unroll
    for (int nt = 0; nt < 8; nt++) {
        mx0 = fmaxf(mx0, fmaxf(s[nt][0], s[nt][1]));
        mx1 = fmaxf(mx1, fmaxf(s[nt][2], s[nt][3]));
    }
    mx0 = fmaxf(mx0, __shfl_xor_sync(0xffffffff, mx0, 1));
    mx0 = fmaxf(mx0, __shfl_xor_sync(0xffffffff, mx0, 2));
    mx1 = fmaxf(mx1, __shfl_xor_sync(0xffffffff, mx1, 1));
    mx1 = fmaxf(mx1, __shfl_xor_sync(0xffffffff, mx1, 2));
    float sum0 = 0.f, sum1 = 0.f;
    #pragma unroll
    for (int nt = 0; nt < 8; nt++) {
        s[nt][0] = __expf(s[nt][0] - mx0); sum0 += s[nt][0];
        s[nt][1] = __expf(s[nt][1] - mx0); sum0 += s[nt][1];
        s[nt][2] = __expf(s[nt][2] - mx1); sum1 += s[nt][2];
        s[nt][3] = __expf(s[nt][3] - mx1); sum1 += s[nt][3];
    }
    sum0 += __shfl_xor_sync(0xffffffff, sum0, 1);
    sum0 += __shfl_xor_sync(0xffffffff, sum0, 2);
    sum1 += __shfl_xor_sync(0xffffffff, sum1, 1);
    sum1 += __shfl_xor_sync(0xffffffff, sum1, 2);
    float inv0 = 1.f / sum0, inv1 = 1.f / sum1;

    // ---- P to smem (tf32), overlaying Q/K region ----
    __syncthreads();                       // everyone done reading Q/K
    #pragma unroll
    for (int nt = 0; nt < 8; nt++) {
        int col = nt * 8 + lc * 2;
        Ps[row0 * PST + col]     = f2tf32(s[nt][0]);
        Ps[row0 * PST + col + 1] = f2tf32(s[nt][1]);
        Ps[row1 * PST + col]     = f2tf32(s[nt][2]);
        Ps[row1 * PST + col + 1] = f2tf32(s[nt][3]);
    }
    __syncwarp();                          // P rows are warp-private

    // ---- O = P V  (M=16, N=32, K=64) ----
    float o[4][4] = {};
    #pragma unroll
    for (int kk = 0; kk < 8; kk++) {
        int k0 = kk * 8;
        uint32_t ap[4];
        ap[0] = Ps[(r_base + lr) * PST + k0 + lc];
        ap[1] = Ps[(r_base + 8 + lr) * PST + k0 + lc];
        ap[2] = Ps[(r_base + lr) * PST + k0 + lc + 4];
        ap[3] = Ps[(r_base + 8 + lr) * PST + k0 + lc + 4];
        #pragma unroll
        for (int nt = 0; nt < 4; nt++) {
            uint32_t b[2];
            b[0] = VT[(nt * 8 + lr) * PST + k0 + lc];
            b[1] = VT[(nt * 8 + lr) * PST + k0 + lc + 4];
            mma_tf32(o[nt], ap, b);
        }
    }

    // ---- epilogue: scale by 1/sum, write g_attn (rolled coords) ----
    {
        int i0 = r_base + lr;              // token index
        int y0 = wy * 8 + (i0 >> 3), x0 = wx * 8 + (i0 & 7);
        int i1 = i0 + 8;
        int y1 = wy * 8 + (i1 >> 3), x1 = wx * 8 + (i1 & 7);
        float* p0 = g_attn + ((size_t)((bb * IMG + y0) * IMG + x0)) * CDIM + head * HD;
        float* p1 = g_attn + ((size_t)((bb * IMG + y1) * IMG + x1)) * CDIM + head * HD;
        #pragma unroll
        for (int nt = 0; nt < 4; nt++) {
            int col = nt * 8 + lc * 2;
            *(float2*)(p0 + col) = make_float2(o[nt][0] * inv0, o[nt][1] * inv0);
            *(float2*)(p1 + col) = make_float2(o[nt][2] * inv1, o[nt][3] * inv1);
        }
    }
}

// ---------------------------------------------------------------------------
// Kernel 3: output projection + bias; roll-back on store. BM=64, 128 thr.
// ---------------------------------------------------------------------------
__global__ __launch_bounds__(128) void out_tc(const float* __restrict__ wout,
                                              const float* __restrict__ bout,
                                              float* __restrict__ out) {
    extern __shared__ uint32_t sm[];
    uint32_t* As = sm;
    uint32_t* Bs = sm + A_WORDS;

    int tid = threadIdx.x;
    int wid = tid >> 5, lane = tid & 31;
    int warp_m = (wid >> 1) * 32;
    int warp_n = (wid & 1) * 32;
    int lr = lane >> 2, lc = lane & 3;
    int m0 = blockIdx.x * 64;

    #pragma unroll
    for (int j = 0; j < 24; j++) {
        int i = tid + j * 128;
        int r = i / 48, c4 = i % 48;
        float4 v = *(const float4*)(g_attn + (size_t)(m0 + r) * CDIM + c4 * 4);
        *(uint4*)&As[r * AST + c4 * 4] =
            make_uint4(f2tf32(v.x), f2tf32(v.y), f2tf32(v.z), f2tf32(v.w));
    }

    for (int t = 0; t < 3; t++) {
        int n0 = t * 64;
        __syncthreads();
        #pragma unroll
        for (int j = 0; j < 24; j++) {
            int i = tid + j * 128;
            int r = i / 48, c4 = i % 48;
            float4 v = *(const float4*)(wout + (size_t)(n0 + r) * CDIM + c4 * 4);
            *(uint4*)&Bs[r * AST + c4 * 4] =
                make_uint4(f2tf32(v.x), f2tf32(v.y), f2tf32(v.z), f2tf32(v.w));
        }
        __syncthreads();

        float acc[2][4][4] = {};
        #pragma unroll
        for (int k0 = 0; k0 < CDIM; k0 += 8) {
            uint32_t a[2][4], b[4][2];
            #pragma unroll
            for (int mt = 0; mt < 2; mt++) {
                int row = warp_m + mt * 16 + lr;
                a[mt][0] = As[row * AST + k0 + lc];
                a[mt][1] = As[(row + 8) * AST + k0 + lc];
                a[mt][2] = As[row * AST + k0 + lc + 4];
                a[mt][3] = As[(row + 8) * AST + k0 + lc + 4];
            }
            #pragma unroll
            for (int nt = 0; nt < 4; nt++) {
                int col = warp_n + nt * 8 + lr;
                b[nt][0] = Bs[col * AST + k0 + lc];
                b[nt][1] = Bs[col * AST + k0 + lc + 4];
            }
            #pragma unroll
            for (int mt = 0; mt < 2; mt++)
                #pragma unroll
                for (int nt = 0; nt < 4; nt++)
                    mma_tf32(acc[mt][nt], a[mt], b[nt]);
        }

        #pragma unroll
        for (int mt = 0; mt < 2; mt++) {
            #pragma unroll
            for (int half = 0; half < 2; half++) {
                int m = m0 + warp_m + mt * 16 + lr + half * 8;
                int bb = m >> 16, y = (m >> 8) & 255, xx = m & 255;
                int yf = (y + DISP) & 255, xf = (xx + DISP) & 255;
                float* op = out + ((size_t)(bb * IMG + yf) * IMG + xf) * CDIM + n0 + warp_n;
                #pragma unroll
                for (int nt = 0; nt < 4; nt++) {
                    int col = nt * 8 + lc * 2;
                    float b0 = bout[n0 + warp_n + col];
                    float b1 = bout[n0 + warp_n + col + 1];
                    *(float2*)(op + col) = make_float2(acc[mt][nt][half * 2] + b0,
                                                       acc[mt][nt][half * 2 + 1] + b1);
                }
            }
        }
    }
}

// ---------------------------------------------------------------------------
extern "C" void kernel_launch(void* const* d_in, const int* in_sizes, int n_in,
                              void* d_out, int out_size) {
    const float* x    = (const float*)d_in[0];
    const float* wqkv = (const float*)d_in[1];
    const float* pos  = (const float*)d_in[2];
    const float* wout = (const float*)d_in[3];
    const float* bout = (const float*)d_in[4];
    float* out = (float*)d_out;

    cudaFuncSetAttribute(qkv_tc, cudaFuncAttributeMaxDynamicSharedMemorySize, SMEM_BYTES);
    cudaFuncSetAttribute(out_tc, cudaFuncAttributeMaxDynamicSharedMemorySize, SMEM_BYTES);

    bias_kernel<<<16, 256>>>(pos);
    qkv_tc<<<MTOT / 64, 128, SMEM_BYTES>>>(x, wqkv);
    attn_mma<<<BATCH * NWIN * HEADS, 128>>>();
    out_tc<<<MTOT / 64, 128, SMEM_BYTES>>>(wout, bout, out);
}